// round 3
// baseline (speedup 1.0000x reference)
#include <cuda_runtime.h>
#include <math.h>

// CPPN fused MLP, fp32-faithful.
// Edge-of-chaos network (gain ~1.4x/layer, 22 layers => ~1600x noise
// amplification) disqualifies tf32/bf16 tensor cores and tanh.approx.
// Speed comes from packed fp32 FFMA2 (fma.rn.f32x2), weights transposed
// k-major in shared so output-neuron pairs are contiguous broadcast LDS.64,
// and 2 points per thread so each weight load feeds 2 FFMA2s.

#define DH    32
#define NHID  22
#define TPB   384
#define GRID  148
// shared floats: WhidT [22][32k][32j] | W1T [11k][32j] | WoutT [32k][4o]
#define SWH_F (NHID * DH * DH)                   // 22528
#define SW1_F (11 * DH)                          // 352
#define SWO_F (DH * 4)                           // 128
#define SMEM_BYTES ((SWH_F + SW1_F + SWO_F) * 4) // 92032 B

typedef unsigned long long u64;

__device__ __forceinline__ u64 dup2(float v) {
    u64 r; asm("mov.b64 %0, {%1, %1};" : "=l"(r) : "f"(v)); return r;
}
__device__ __forceinline__ void ffma2(u64& acc, u64 a, u64 b) {
    asm("fma.rn.f32x2 %0, %1, %2, %0;" : "+l"(acc) : "l"(a), "l"(b));
}
__device__ __forceinline__ void unpk(u64 v, float& lo, float& hi) {
    asm("mov.b64 {%0, %1}, %2;" : "=f"(lo), "=f"(hi) : "l"(v));
}
__device__ __forceinline__ float sigmoidf_acc(float v) {
    return 1.0f / (1.0f + expf(-v));
}

__global__ void __launch_bounds__(TPB, 1)
cppn_kernel(const float* __restrict__ x,
            const float* __restrict__ W1,
            const float* __restrict__ Wh,
            const float* __restrict__ Wo,
            float* __restrict__ out, int n)
{
    extern __shared__ float sm[];
    float* sWh = sm;                 // [L][k][j], j contiguous
    float* sW1 = sm + SWH_F;         // [k][j]
    float* sWo = sW1 + SW1_F;        // [k][4]  (o = 0..2, o=3 pad)

    // cooperative load + transpose (once per persistent CTA)
    for (int idx = threadIdx.x; idx < SWH_F; idx += TPB) {
        int L = idx >> 10, r = idx & 1023, j = r >> 5, k = r & 31;
        sWh[(L << 10) + (k << 5) + j] = Wh[idx];
    }
    for (int idx = threadIdx.x; idx < DH * 11; idx += TPB) {
        int j = idx / 11, k = idx - j * 11;
        sW1[k * DH + j] = W1[idx];
    }
    for (int idx = threadIdx.x; idx < 4 * DH; idx += TPB) {
        int k = idx >> 2, o = idx & 3;
        sWo[idx] = (o < 3) ? Wo[o * DH + k] : 0.0f;
    }
    __syncthreads();

    const int stride = GRID * TPB * 2;
    for (int base = blockIdx.x * (TPB * 2); base < n; base += stride) {
        const int pA = base + (int)threadIdx.x;
        const int pB = pA + TPB;
        const bool vA = (pA < n), vB = (pB < n);

        float hA[DH], hB[DH];

        // ---------------- layer 1: 11 -> 32, tanh ----------------
        {
            float xA[11], xB[11];
            #pragma unroll
            for (int k = 0; k < 11; k++) {
                xA[k] = vA ? x[pA * 11 + k] : 0.0f;
                xB[k] = vB ? x[pB * 11 + k] : 0.0f;
            }
            u64 aA[16], aB[16];
            #pragma unroll
            for (int j = 0; j < 16; j++) { aA[j] = 0ull; aB[j] = 0ull; }
            const u64* w = (const u64*)sW1;
            #pragma unroll
            for (int k = 0; k < 11; k++) {
                u64 a2 = dup2(xA[k]), b2 = dup2(xB[k]);
                #pragma unroll
                for (int j = 0; j < 16; j++) {
                    u64 wv = w[k * 16 + j];
                    ffma2(aA[j], a2, wv);
                    ffma2(aB[j], b2, wv);
                }
            }
            #pragma unroll
            for (int j = 0; j < 16; j++) {
                float l0, h0; unpk(aA[j], l0, h0);
                hA[2 * j] = tanhf(l0); hA[2 * j + 1] = tanhf(h0);
                float l1, h1; unpk(aB[j], l1, h1);
                hB[2 * j] = tanhf(l1); hB[2 * j + 1] = tanhf(h1);
            }
        }

        // ---------------- 22 hidden layers: 32 -> 32, tanh ----------------
        for (int L = 0; L < NHID; ++L) {
            const u64* w = (const u64*)(sWh + (L << 10));
            u64 aA[16], aB[16];
            #pragma unroll
            for (int j = 0; j < 16; j++) { aA[j] = 0ull; aB[j] = 0ull; }
            #pragma unroll
            for (int k = 0; k < DH; k++) {
                u64 a2 = dup2(hA[k]), b2 = dup2(hB[k]);
                #pragma unroll
                for (int j = 0; j < 16; j++) {
                    u64 wv = w[k * 16 + j];
                    ffma2(aA[j], a2, wv);
                    ffma2(aB[j], b2, wv);
                }
            }
            #pragma unroll
            for (int j = 0; j < 16; j++) {
                float l0, h0; unpk(aA[j], l0, h0);
                hA[2 * j] = tanhf(l0); hA[2 * j + 1] = tanhf(h0);
                float l1, h1; unpk(aB[j], l1, h1);
                hB[2 * j] = tanhf(l1); hB[2 * j + 1] = tanhf(h1);
            }
        }

        // ---------------- output: 32 -> 3, sigmoid ----------------
        {
            const u64* w = (const u64*)sWo;   // [k][2] u64 per row
            u64 oA0 = 0ull, oA1 = 0ull, oB0 = 0ull, oB1 = 0ull;
            #pragma unroll
            for (int k = 0; k < DH; k++) {
                u64 w0 = w[2 * k], w1 = w[2 * k + 1];
                u64 a2 = dup2(hA[k]), b2 = dup2(hB[k]);
                ffma2(oA0, a2, w0);
                ffma2(oA1, a2, w1);
                ffma2(oB0, b2, w0);
                ffma2(oB1, b2, w1);
            }
            float a0, a1, a2f, adum, b0, b1, b2f, bdum;
            unpk(oA0, a0, a1); unpk(oA1, a2f, adum);
            unpk(oB0, b0, b1); unpk(oB1, b2f, bdum);
            if (vA) {
                out[3 * pA + 0] = sigmoidf_acc(a0);
                out[3 * pA + 1] = sigmoidf_acc(a1);
                out[3 * pA + 2] = sigmoidf_acc(a2f);
            }
            if (vB) {
                out[3 * pB + 0] = sigmoidf_acc(b0);
                out[3 * pB + 1] = sigmoidf_acc(b1);
                out[3 * pB + 2] = sigmoidf_acc(b2f);
            }
        }
    }
}

extern "C" void kernel_launch(void* const* d_in, const int* in_sizes, int n_in,
                              void* d_out, int out_size)
{
    const float* x  = (const float*)d_in[0];
    const float* W1 = (const float*)d_in[1];
    const float* Wh = (const float*)d_in[2];
    const float* Wo = (const float*)d_in[3];
    float* out = (float*)d_out;

    const int n = in_sizes[0] / 11;   // number of points

    cudaFuncSetAttribute(cppn_kernel,
                         cudaFuncAttributeMaxDynamicSharedMemorySize,
                         SMEM_BYTES);
    cppn_kernel<<<GRID, TPB, SMEM_BYTES>>>(x, W1, Wh, Wo, out, n);
}